// round 14
// baseline (speedup 1.0000x reference)
#include <cuda_runtime.h>
#include <math.h>
#include <stdint.h>

#define L_DIM 16384
#define Q_DIM (L_DIM / 4)          // 4096 quads per row
#define HALF_Q (Q_DIM / 2)         // 2048 quads = 32 KB per half
#define B_DIM 64
#define N_ROWS 1024
#define TOTAL_BLOCKS (N_ROWS + B_DIM)   // 1088
#define THREADS 256
#define ITERS_L (HALF_Q / THREADS) // 8 quads/thread (LDG half)
#define DEPTH 4
#define GROUPS (ITERS_L / DEPTH)   // 2
#define ITERS_M (Q_DIM / THREADS)  // 16 (mask rows, full row via LDG)
#define CAP 1024
#define THR_FIXED 2.0f
#define HALF_BYTES (HALF_Q * 16)   // 32768

// Scratch (allocation-free rule: __device__ globals)
__device__ float g_nmask[B_DIM];
__device__ float g_sp2[N_ROWS];
__device__ float g_spm[N_ROWS];
__device__ unsigned int g_done = 0;

// ---- TMA / mbarrier helpers ----
__device__ __forceinline__ uint32_t smem_u32(const void* p) {
    return (uint32_t)__cvta_generic_to_shared(p);
}
__device__ __forceinline__ void mbar_init(uint32_t mbar, uint32_t cnt) {
    asm volatile("mbarrier.init.shared.b64 [%0], %1;" :: "r"(mbar), "r"(cnt) : "memory");
}
__device__ __forceinline__ void mbar_expect_tx(uint32_t mbar, uint32_t bytes) {
    asm volatile("mbarrier.arrive.expect_tx.shared.b64 _, [%0], %1;"
                 :: "r"(mbar), "r"(bytes) : "memory");
}
__device__ __forceinline__ void bulk_g2s(uint32_t dst, const void* src, uint32_t bytes, uint32_t mbar) {
    asm volatile("cp.async.bulk.shared::cluster.global.mbarrier::complete_tx::bytes [%0], [%1], %2, [%3];"
                 :: "r"(dst), "l"(src), "r"(bytes), "r"(mbar) : "memory");
}
__device__ __forceinline__ void mbar_wait(uint32_t mbar, uint32_t parity) {
    asm volatile(
        "{\n\t"
        ".reg .pred P;\n\t"
        "WAIT_%=:\n\t"
        "mbarrier.try_wait.parity.acquire.cta.shared::cta.b64 P, [%0], %1, 0x989680;\n\t"
        "@P bra DONE_%=;\n\t"
        "bra WAIT_%=;\n\t"
        "DONE_%=:\n\t"
        "}"
        :: "r"(mbar), "r"(parity) : "memory");
}

__global__ void __launch_bounds__(THREADS, 4) fused_kernel(
    const float* __restrict__ logits,
    const float* __restrict__ mask,
    float* __restrict__ out)
{
    __shared__ __align__(128) float4 tbuf[HALF_Q];   // 32 KB TMA landing zone
    __shared__ __align__(8) unsigned long long mbar_storage;
    __shared__ float sval[CAP];
    __shared__ int   sidx[CAP];
    __shared__ int   s_cnt;
    __shared__ float s_red[THREADS / 32];
    __shared__ float s_max;
    __shared__ float s_fin[THREADS];
    __shared__ unsigned int s_ticket;

    const int blk  = blockIdx.x;
    const int tid  = threadIdx.x;
    const int warp = tid >> 5, lane = tid & 31;

    if (blk >= N_ROWS) {
        // --------- mask-sum block (one per batch row), pipelined LDG --------
        const int b = blk - N_ROWS;
        const float4* m4 = (const float4*)(mask + (size_t)b * L_DIM);
        float4 a[DEPTH], nb[DEPTH];
        #pragma unroll
        for (int k = 0; k < DEPTH; k++) a[k] = m4[tid + k * THREADS];
        float s = 0.f;
        #pragma unroll
        for (int g = 0; g < ITERS_M / DEPTH; g++) {
            if (g + 1 < ITERS_M / DEPTH) {
                #pragma unroll
                for (int k = 0; k < DEPTH; k++) nb[k] = m4[tid + ((g + 1) * DEPTH + k) * THREADS];
            }
            #pragma unroll
            for (int k = 0; k < DEPTH; k++) s += (a[k].x + a[k].y) + (a[k].z + a[k].w);
            #pragma unroll
            for (int k = 0; k < DEPTH; k++) a[k] = nb[k];
        }
        #pragma unroll
        for (int o = 16; o; o >>= 1) s += __shfl_xor_sync(0xffffffffu, s, o);
        if (lane == 0) s_red[warp] = s;
        __syncthreads();
        if (tid == 0) {
            float t = 0.f;
            #pragma unroll
            for (int w = 0; w < THREADS / 32; w++) t += s_red[w];
            g_nmask[b] = t;
        }
    } else {
        // ----------------------- row block (b,k) ---------------------------
        const int row = blk;
        const float4* z4 = (const float4*)(logits + (size_t)row * L_DIM);

        // ---- post the TMA fetch of the 2nd half before touching the 1st ----
        if (tid == 0) {
            mbar_init(smem_u32(&mbar_storage), 1);
            s_cnt = 0;
        }
        __syncthreads();
        if (tid == 0) {
            uint32_t mb = smem_u32(&mbar_storage);
            mbar_expect_tx(mb, HALF_BYTES);
            bulk_g2s(smem_u32(tbuf), z4 + HALF_Q, HALF_BYTES, mb);
        }

        // ---- LDG half: pipelined stream, branch-free max + flag bits ----
        float4 a[DEPTH], nb[DEPTH];
        #pragma unroll
        for (int k = 0; k < DEPTH; k++) a[k] = z4[tid + k * THREADS];
        float m = -3.4e38f;
        unsigned int qmask = 0u;
        #pragma unroll
        for (int g = 0; g < GROUPS; g++) {
            if (g + 1 < GROUPS) {
                #pragma unroll
                for (int k = 0; k < DEPTH; k++) nb[k] = z4[tid + ((g + 1) * DEPTH + k) * THREADS];
            }
            #pragma unroll
            for (int k = 0; k < DEPTH; k++) {
                float vm = fmaxf(fmaxf(a[k].x, a[k].y), fmaxf(a[k].z, a[k].w));
                m = fmaxf(m, vm);
                qmask |= (vm > THR_FIXED ? 1u : 0u) << (g * DEPTH + k);
            }
            #pragma unroll
            for (int k = 0; k < DEPTH; k++) a[k] = nb[k];
        }

        // ---- TMA half: wait once, consume from smem (divergent pushes OK) ----
        mbar_wait(smem_u32(&mbar_storage), 0);
        #pragma unroll
        for (int j = 0; j < ITERS_L; j++) {
            int sq = tid + j * THREADS;          // quad within the smem half
            float4 v = tbuf[sq];
            float vm = fmaxf(fmaxf(v.x, v.y), fmaxf(v.z, v.w));
            m = fmaxf(m, vm);
            if (vm > THR_FIXED) {
                int base = 4 * (HALF_Q + sq);    // element index within row
                if (v.x > THR_FIXED) { int p = atomicAdd(&s_cnt, 1); if (p < CAP) { sval[p] = v.x; sidx[p] = base + 0; } }
                if (v.y > THR_FIXED) { int p = atomicAdd(&s_cnt, 1); if (p < CAP) { sval[p] = v.y; sidx[p] = base + 1; } }
                if (v.z > THR_FIXED) { int p = atomicAdd(&s_cnt, 1); if (p < CAP) { sval[p] = v.z; sidx[p] = base + 2; } }
                if (v.w > THR_FIXED) { int p = atomicAdd(&s_cnt, 1); if (p < CAP) { sval[p] = v.w; sidx[p] = base + 3; } }
            }
        }

        // ---- block max reduce ----
        #pragma unroll
        for (int o = 16; o; o >>= 1) m = fmaxf(m, __shfl_xor_sync(0xffffffffu, m, o));
        if (lane == 0) s_red[warp] = m;
        __syncthreads();
        if (tid == 0) {
            float t = s_red[0];
            #pragma unroll
            for (int w = 1; w < THREADS / 32; w++) t = fmaxf(t, s_red[w]);
            s_max = t;
        }
        __syncthreads();
        const float supp_thr = s_max - 1.0f;   // support ⊆ {z > max-1}

        if (supp_thr >= THR_FIXED) {
            // ---- LDG-half revisit: only flagged quads (L1/L2 hot) ----
            unsigned int qm = qmask;
            while (qm) {
                int j = __ffs(qm) - 1;
                qm &= qm - 1u;
                int i = tid + j * THREADS;
                float4 q = z4[i];
                if (q.x > supp_thr) { int p = atomicAdd(&s_cnt, 1); if (p < CAP) { sval[p] = q.x; sidx[p] = 4 * i + 0; } }
                if (q.y > supp_thr) { int p = atomicAdd(&s_cnt, 1); if (p < CAP) { sval[p] = q.y; sidx[p] = 4 * i + 1; } }
                if (q.z > supp_thr) { int p = atomicAdd(&s_cnt, 1); if (p < CAP) { sval[p] = q.z; sidx[p] = 4 * i + 2; } }
                if (q.w > supp_thr) { int p = atomicAdd(&s_cnt, 1); if (p < CAP) { sval[p] = q.w; sidx[p] = 4 * i + 3; } }
            }
            __syncthreads();
        }
        if (supp_thr < THR_FIXED || s_cnt >= CAP) {
            // ---- fallback (≈never): full re-gather from global at supp_thr ----
            __syncthreads();
            if (tid == 0) s_cnt = 0;
            __syncthreads();
            #pragma unroll 4
            for (int it = 0; it < 2 * ITERS_L; it++) {
                int i = tid + it * THREADS;
                float4 q = z4[i];
                if (q.x > supp_thr) { int p = atomicAdd(&s_cnt, 1); if (p < CAP) { sval[p] = q.x; sidx[p] = 4 * i + 0; } }
                if (q.y > supp_thr) { int p = atomicAdd(&s_cnt, 1); if (p < CAP) { sval[p] = q.y; sidx[p] = 4 * i + 1; } }
                if (q.z > supp_thr) { int p = atomicAdd(&s_cnt, 1); if (p < CAP) { sval[p] = q.z; sidx[p] = 4 * i + 2; } }
                if (q.w > supp_thr) { int p = atomicAdd(&s_cnt, 1); if (p < CAP) { sval[p] = q.w; sidx[p] = 4 * i + 3; } }
            }
            __syncthreads();
        }
        const int cnt = min(s_cnt, CAP);

        // ---- warp 0: Michelot from tau0 = max-1, then loss terms ----
        if (warp == 0) {
            float tau = supp_thr;   // tau* >= max-1; candidates ⊇ support
            for (int iter = 0; iter < 64; iter++) {
                float s = 0.f; int c = 0;
                for (int i = lane; i < cnt; i += 32) {
                    float vv = sval[i];
                    if (vv > tau) { s += vv; c++; }
                }
                #pragma unroll
                for (int o = 16; o; o >>= 1) {
                    s += __shfl_xor_sync(0xffffffffu, s, o);
                    c += __shfl_xor_sync(0xffffffffu, c, o);
                }
                float nt = (s - 1.0f) / (float)c;   // c >= 1 (argmax active)
                if (nt == tau) break;
                tau = nt;
            }

            const int b = row >> 4;
            const float* mrow = mask + (size_t)b * L_DIM;
            float sp2 = 0.f, spm = 0.f;
            for (int i = lane; i < cnt; i += 32) {
                float p = sval[i] - tau;
                if (p > 0.f) {                       // only true support gathers mask
                    sp2 += p * p;
                    spm += mrow[sidx[i]] * p;        // mask is 0/1
                }
            }
            #pragma unroll
            for (int o = 16; o; o >>= 1) {
                sp2 += __shfl_xor_sync(0xffffffffu, sp2, o);
                spm += __shfl_xor_sync(0xffffffffu, spm, o);
            }
            if (lane == 0) {
                g_sp2[row] = sp2;
                g_spm[row] = spm;
            }
        }
    }

    // ------------- last-block-done final reduction (deterministic) ---------
    __syncthreads();
    __threadfence();
    if (tid == 0) s_ticket = atomicAdd(&g_done, 1u);
    __syncthreads();
    if (s_ticket == TOTAL_BLOCKS - 1) {
        float acc = 0.f;
        #pragma unroll
        for (int j = 0; j < N_ROWS / THREADS; j++) {
            int r = tid + j * THREADS;
            int b = r >> 4;
            float inv_n = 1.0f / fmaxf(g_nmask[b], 1e-12f);
            // sum_L (p-q)^2 = sum p^2 - 2*inv_n*spm + 1/n
            acc += 0.5f * g_sp2[r] - inv_n * g_spm[r] + 0.5f * inv_n;
        }
        s_fin[tid] = acc;
        __syncthreads();
        #pragma unroll
        for (int o = THREADS / 2; o > 0; o >>= 1) {
            if (tid < o) s_fin[tid] += s_fin[tid + o];
            __syncthreads();
        }
        if (tid == 0) {
            out[0] = s_fin[0] * (1.0f / (float)N_ROWS);
            g_done = 0;        // reset for next graph replay
        }
    }
}

// ---------------------------------------------------------------------------
extern "C" void kernel_launch(void* const* d_in, const int* in_sizes, int n_in,
                              void* d_out, int out_size) {
    const float* logits = (const float*)d_in[0];   // (64,16,16384) fp32
    const float* mask   = (const float*)d_in[1];   // (64,16384) fp32
    float* out = (float*)d_out;

    fused_kernel<<<TOTAL_BLOCKS, THREADS>>>(logits, mask, out);
}

// round 16
// speedup vs baseline: 1.7143x; 1.7143x over previous
#include <cuda_runtime.h>
#include <math.h>
#include <stdint.h>

#define L_DIM 16384
#define Q_DIM (L_DIM / 4)          // 4096 float4 per row
#define O_DIM (L_DIM / 8)          // 2048 octs (32B) per row
#define B_DIM 64
#define K_DIM 16
#define N_ROWS 1024
#define MASK_BLOCKS B_DIM
#define TOTAL_BLOCKS (N_ROWS + MASK_BLOCKS)   // 1088
#define THREADS 256
#define OITERS (O_DIM / THREADS)   // 8 octs per thread
#define DEPTH 2                    // octs in flight (64 B / thread)
#define GROUPS (OITERS / DEPTH)    // 4
#define CAP 1024
#define THR_FIXED 2.0f             // speculative flag threshold (N(0,1) logits)

// Scratch (allocation-free rule: __device__ globals)
__device__ float g_nmask[B_DIM];
__device__ float g_sp2[N_ROWS];
__device__ float g_spm[N_ROWS];
__device__ unsigned int g_done = 0;

// 256-bit L2-persistent load (sm_103a: evict_last requires .v4.b64/.v8.b32).
// Doubles bytes-per-request vs LDG.128 AND marks lines evict_last so the
// 68 MB working set stays L2-resident across graph replays.
__device__ __forceinline__ void ldg256_keep(const float* p, float4& lo, float4& hi) {
    unsigned long long u0, u1, u2, u3;
    asm("ld.global.nc.L2::evict_last.v4.b64 {%0,%1,%2,%3}, [%4];"
        : "=l"(u0), "=l"(u1), "=l"(u2), "=l"(u3) : "l"(p));
    lo.x = __uint_as_float((unsigned int)u0);  lo.y = __uint_as_float((unsigned int)(u0 >> 32));
    lo.z = __uint_as_float((unsigned int)u1);  lo.w = __uint_as_float((unsigned int)(u1 >> 32));
    hi.x = __uint_as_float((unsigned int)u2);  hi.y = __uint_as_float((unsigned int)(u2 >> 32));
    hi.z = __uint_as_float((unsigned int)u3);  hi.w = __uint_as_float((unsigned int)(u3 >> 32));
}

__global__ void __launch_bounds__(THREADS, 4) fused_kernel(
    const float* __restrict__ logits,
    const float* __restrict__ mask,
    float* __restrict__ out)
{
    __shared__ float sval[CAP];
    __shared__ int   sidx[CAP];
    __shared__ int   s_cnt;
    __shared__ float s_red[THREADS / 32];
    __shared__ float s_max;
    __shared__ float s_fin[THREADS];
    __shared__ unsigned int s_ticket;

    const int blk  = blockIdx.x;
    const int tid  = threadIdx.x;
    const int warp = tid >> 5, lane = tid & 31;

    if (blk >= N_ROWS) {
        // --------- mask-sum block (one per batch row), LDG.256 pipelined ----
        const int b = blk - N_ROWS;
        const float* mrow = mask + (size_t)b * L_DIM;
        float4 a0[DEPTH], a1[DEPTH], n0[DEPTH], n1[DEPTH];
        #pragma unroll
        for (int k = 0; k < DEPTH; k++)
            ldg256_keep(mrow + 8 * (tid + k * THREADS), a0[k], a1[k]);
        float s = 0.f;
        #pragma unroll
        for (int g = 0; g < GROUPS; g++) {
            if (g + 1 < GROUPS) {
                #pragma unroll
                for (int k = 0; k < DEPTH; k++)
                    ldg256_keep(mrow + 8 * (tid + ((g + 1) * DEPTH + k) * THREADS), n0[k], n1[k]);
            }
            #pragma unroll
            for (int k = 0; k < DEPTH; k++) {
                s += (a0[k].x + a0[k].y) + (a0[k].z + a0[k].w)
                   + (a1[k].x + a1[k].y) + (a1[k].z + a1[k].w);
            }
            #pragma unroll
            for (int k = 0; k < DEPTH; k++) { a0[k] = n0[k]; a1[k] = n1[k]; }
        }
        #pragma unroll
        for (int o = 16; o; o >>= 1) s += __shfl_xor_sync(0xffffffffu, s, o);
        if (lane == 0) s_red[warp] = s;
        __syncthreads();
        if (tid == 0) {
            float t = 0.f;
            #pragma unroll
            for (int w = 0; w < THREADS / 32; w++) t += s_red[w];
            g_nmask[b] = t;
        }
    } else {
        // ----------------------- row block (b,k) ---------------------------
        const int row = blk;
        const float* zrow = logits + (size_t)row * L_DIM;
        const float4* z4 = (const float4*)zrow;
        if (tid == 0) s_cnt = 0;

        // ---- pass 1: LDG.256 pipelined stream, branch-free max + oct flags ----
        float4 a0[DEPTH], a1[DEPTH], n0[DEPTH], n1[DEPTH];
        #pragma unroll
        for (int k = 0; k < DEPTH; k++)
            ldg256_keep(zrow + 8 * (tid + k * THREADS), a0[k], a1[k]);
        float m = -3.4e38f;
        unsigned int qmask = 0u;   // one bit per oct (8 octs/thread)
        #pragma unroll
        for (int g = 0; g < GROUPS; g++) {
            if (g + 1 < GROUPS) {
                #pragma unroll
                for (int k = 0; k < DEPTH; k++)
                    ldg256_keep(zrow + 8 * (tid + ((g + 1) * DEPTH + k) * THREADS), n0[k], n1[k]);
            }
            #pragma unroll
            for (int k = 0; k < DEPTH; k++) {
                float vm0 = fmaxf(fmaxf(a0[k].x, a0[k].y), fmaxf(a0[k].z, a0[k].w));
                float vm1 = fmaxf(fmaxf(a1[k].x, a1[k].y), fmaxf(a1[k].z, a1[k].w));
                float vm = fmaxf(vm0, vm1);
                m = fmaxf(m, vm);
                qmask |= (vm > THR_FIXED ? 1u : 0u) << (g * DEPTH + k);
            }
            #pragma unroll
            for (int k = 0; k < DEPTH; k++) { a0[k] = n0[k]; a1[k] = n1[k]; }
        }
        #pragma unroll
        for (int o = 16; o; o >>= 1) m = fmaxf(m, __shfl_xor_sync(0xffffffffu, m, o));
        if (lane == 0) s_red[warp] = m;
        __syncthreads();
        if (tid == 0) {
            float t = s_red[0];
            #pragma unroll
            for (int w = 1; w < THREADS / 32; w++) t = fmaxf(t, s_red[w]);
            s_max = t;
        }
        __syncthreads();
        const float supp_thr = s_max - 1.0f;   // support ⊆ {z > max-1}

        if (supp_thr >= THR_FIXED) {
            // ---- pass 2 (fast path): revisit only flagged octs (L1/L2-hot) ----
            unsigned int qm = qmask;
            while (qm) {
                int j = __ffs(qm) - 1;
                qm &= qm - 1u;
                int oi = tid + j * THREADS;        // oct index in row
                #pragma unroll
                for (int h = 0; h < 2; h++) {
                    float4 q = z4[2 * oi + h];
                    int base = 8 * oi + 4 * h;
                    if (q.x > supp_thr) { int p = atomicAdd(&s_cnt, 1); if (p < CAP) { sval[p] = q.x; sidx[p] = base + 0; } }
                    if (q.y > supp_thr) { int p = atomicAdd(&s_cnt, 1); if (p < CAP) { sval[p] = q.y; sidx[p] = base + 1; } }
                    if (q.z > supp_thr) { int p = atomicAdd(&s_cnt, 1); if (p < CAP) { sval[p] = q.z; sidx[p] = base + 2; } }
                    if (q.w > supp_thr) { int p = atomicAdd(&s_cnt, 1); if (p < CAP) { sval[p] = q.w; sidx[p] = base + 3; } }
                }
            }
            __syncthreads();
        }
        if (supp_thr < THR_FIXED || s_cnt >= CAP) {
            // ---- fallback (≈never): full re-gather from L2 at supp_thr ----
            __syncthreads();
            if (tid == 0) s_cnt = 0;
            __syncthreads();
            #pragma unroll 4
            for (int it = 0; it < Q_DIM / THREADS; it++) {
                int i = tid + it * THREADS;
                float4 q = z4[i];
                if (q.x > supp_thr) { int p = atomicAdd(&s_cnt, 1); if (p < CAP) { sval[p] = q.x; sidx[p] = 4 * i + 0; } }
                if (q.y > supp_thr) { int p = atomicAdd(&s_cnt, 1); if (p < CAP) { sval[p] = q.y; sidx[p] = 4 * i + 1; } }
                if (q.z > supp_thr) { int p = atomicAdd(&s_cnt, 1); if (p < CAP) { sval[p] = q.z; sidx[p] = 4 * i + 2; } }
                if (q.w > supp_thr) { int p = atomicAdd(&s_cnt, 1); if (p < CAP) { sval[p] = q.w; sidx[p] = 4 * i + 3; } }
            }
            __syncthreads();
        }
        const int cnt = min(s_cnt, CAP);

        // ---- warp 0: Michelot iteration (start at tau = max-1), loss terms ----
        if (warp == 0) {
            float tau = supp_thr;   // tau* >= max-1; candidate set ⊇ support, nonempty
            for (int iter = 0; iter < 64; iter++) {
                float s = 0.f; int c = 0;
                for (int i = lane; i < cnt; i += 32) {
                    float vv = sval[i];
                    if (vv > tau) { s += vv; c++; }
                }
                #pragma unroll
                for (int o = 16; o; o >>= 1) {
                    s += __shfl_xor_sync(0xffffffffu, s, o);
                    c += __shfl_xor_sync(0xffffffffu, c, o);
                }
                float nt = (s - 1.0f) / (float)c;
                if (nt == tau) break;
                tau = nt;
            }

            const int b = row >> 4;
            const float* mrow = mask + (size_t)b * L_DIM;
            float sp2 = 0.f, spm = 0.f;
            for (int i = lane; i < cnt; i += 32) {
                float p = sval[i] - tau;
                if (p > 0.f) {
                    sp2 += p * p;
                    spm += mrow[sidx[i]] * p;   // mask is 0/1; inv_n applied at the end
                }
            }
            #pragma unroll
            for (int o = 16; o; o >>= 1) {
                sp2 += __shfl_xor_sync(0xffffffffu, sp2, o);
                spm += __shfl_xor_sync(0xffffffffu, spm, o);
            }
            if (lane == 0) {
                g_sp2[row] = sp2;
                g_spm[row] = spm;
            }
        }
    }

    // ------------- last-block-done final reduction (deterministic) ---------
    __syncthreads();
    __threadfence();
    if (tid == 0) s_ticket = atomicAdd(&g_done, 1u);
    __syncthreads();
    if (s_ticket == TOTAL_BLOCKS - 1) {
        float acc = 0.f;
        #pragma unroll
        for (int j = 0; j < N_ROWS / THREADS; j++) {
            int r = tid + j * THREADS;
            int b = r >> 4;
            float inv_n = 1.0f / fmaxf(g_nmask[b], 1e-12f);
            // sum_L (p-q)^2 = sum p^2 - 2*inv_n*spm + 1/n
            acc += 0.5f * g_sp2[r] - inv_n * g_spm[r] + 0.5f * inv_n;
        }
        s_fin[tid] = acc;
        __syncthreads();
        #pragma unroll
        for (int o = THREADS / 2; o > 0; o >>= 1) {
            if (tid < o) s_fin[tid] += s_fin[tid + o];
            __syncthreads();
        }
        if (tid == 0) {
            out[0] = s_fin[0] * (1.0f / (float)N_ROWS);
            g_done = 0;        // reset for next graph replay
        }
    }
}

// ---------------------------------------------------------------------------
extern "C" void kernel_launch(void* const* d_in, const int* in_sizes, int n_in,
                              void* d_out, int out_size) {
    const float* logits = (const float*)d_in[0];   // (64,16,16384) fp32
    const float* mask   = (const float*)d_in[1];   // (64,16384) fp32
    float* out = (float*)d_out;

    fused_kernel<<<TOTAL_BLOCKS, THREADS>>>(logits, mask, out);
}

// round 17
// speedup vs baseline: 1.7802x; 1.0385x over previous
#include <cuda_runtime.h>
#include <math.h>
#include <stdint.h>

#define L_DIM 16384
#define Q_DIM (L_DIM / 4)
#define B_DIM 64
#define N_ROWS 1024
#define ROW_CTAS (N_ROWS / 2)      // 512 (2 rows per CTA)
#define MASK_CTAS (B_DIM / 2)      // 32 (2 mask rows per CTA)
#define TOTAL_BLOCKS (ROW_CTAS + MASK_CTAS)   // 544 = one wave @ 4 CTA/SM
#define THREADS 256
#define ITERS 16                   // quads per thread per row
#define DEPTH 4
#define GROUPS (ITERS / DEPTH)     // 4
#define CAP 640                    // per-row candidate cap (expect ~373 @ thr=2.0)
#define THR_FIXED 2.0f

// Scratch (allocation-free rule: __device__ globals)
__device__ float g_nmask[B_DIM];
__device__ float g_sp2[N_ROWS];
__device__ float g_spm[N_ROWS];
__device__ unsigned int g_done = 0;

__global__ void __launch_bounds__(THREADS, 4) fused_kernel(
    const float* __restrict__ logits,
    const float* __restrict__ mask,
    float* __restrict__ out)
{
    __shared__ float sval[2][CAP];
    __shared__ int   sidx[2][CAP];
    __shared__ int   s_cnt[2];
    __shared__ float s_red[THREADS / 32];
    __shared__ float s_max;
    __shared__ float s_fin[THREADS];
    __shared__ unsigned int s_ticket;

    const int blk  = blockIdx.x;
    const int tid  = threadIdx.x;
    const int warp = tid >> 5, lane = tid & 31;

    if (blk >= ROW_CTAS) {
        // --------- mask CTA: sum two mask rows, pipelined ----------
        #pragma unroll
        for (int half = 0; half < 2; half++) {
            const int b = (blk - ROW_CTAS) * 2 + half;
            const float4* m4 = (const float4*)(mask + (size_t)b * L_DIM);
            float4 a[DEPTH], nb[DEPTH];
            #pragma unroll
            for (int k = 0; k < DEPTH; k++) a[k] = m4[tid + k * THREADS];
            float s = 0.f;
            #pragma unroll
            for (int g = 0; g < GROUPS; g++) {
                if (g + 1 < GROUPS) {
                    #pragma unroll
                    for (int k = 0; k < DEPTH; k++) nb[k] = m4[tid + ((g + 1) * DEPTH + k) * THREADS];
                }
                #pragma unroll
                for (int k = 0; k < DEPTH; k++) s += (a[k].x + a[k].y) + (a[k].z + a[k].w);
                #pragma unroll
                for (int k = 0; k < DEPTH; k++) a[k] = nb[k];
            }
            #pragma unroll
            for (int o = 16; o; o >>= 1) s += __shfl_xor_sync(0xffffffffu, s, o);
            if (lane == 0) s_red[warp] = s;
            __syncthreads();
            if (tid == 0) {
                float t = 0.f;
                #pragma unroll
                for (int w = 0; w < THREADS / 32; w++) t += s_red[w];
                g_nmask[b] = t;
            }
            __syncthreads();
        }
    } else {
        const int r0 = blk * 2, r1 = blk * 2 + 1;
        const float4* za = (const float4*)(logits + (size_t)r0 * L_DIM);
        const float4* zb = (const float4*)(logits + (size_t)r1 * L_DIM);
        if (tid == 0) { s_cnt[0] = 0; s_cnt[1] = 0; }

        float4 a[DEPTH], nb[DEPTH];
        float m;
        unsigned int qmask;

        // ================== row 0 stream ==================
        #pragma unroll
        for (int k = 0; k < DEPTH; k++) a[k] = za[tid + k * THREADS];
        m = -3.4e38f; qmask = 0u;
        #pragma unroll
        for (int g = 0; g < GROUPS; g++) {
            if (g + 1 < GROUPS) {
                #pragma unroll
                for (int k = 0; k < DEPTH; k++) nb[k] = za[tid + ((g + 1) * DEPTH + k) * THREADS];
            }
            #pragma unroll
            for (int k = 0; k < DEPTH; k++) {
                float vm = fmaxf(fmaxf(a[k].x, a[k].y), fmaxf(a[k].z, a[k].w));
                m = fmaxf(m, vm);
                qmask |= (vm > THR_FIXED ? 1u : 0u) << (g * DEPTH + k);
            }
            #pragma unroll
            for (int k = 0; k < DEPTH; k++) a[k] = nb[k];
        }

        // ---- prime row1 (2 groups = 8 LDG.128) BEFORE row0's tail ----
        // These stay in flight across the whole tail: DRAM keeps streaming.
        float4 p0[DEPTH], p1[DEPTH];
        #pragma unroll
        for (int k = 0; k < DEPTH; k++) p0[k] = zb[tid + k * THREADS];
        #pragma unroll
        for (int k = 0; k < DEPTH; k++) p1[k] = zb[tid + (DEPTH + k) * THREADS];

        // ================== row 0 tail ==================
        float m0w = m;
        #pragma unroll
        for (int o = 16; o; o >>= 1) m0w = fmaxf(m0w, __shfl_xor_sync(0xffffffffu, m0w, o));
        if (lane == 0) s_red[warp] = m0w;
        __syncthreads();
        if (tid == 0) {
            float t = s_red[0];
            #pragma unroll
            for (int w = 1; w < THREADS / 32; w++) t = fmaxf(t, s_red[w]);
            s_max = t;
        }
        __syncthreads();
        const float thr0 = s_max - 1.0f;   // support ⊆ {z > max-1}
        const bool fb0 = (thr0 < THR_FIXED);
        if (!fb0) {
            unsigned int qm = qmask;
            while (qm) {
                int j = __ffs(qm) - 1;
                qm &= qm - 1u;
                int i = tid + j * THREADS;
                float4 q = za[i];   // L1/L2 hot
                if (q.x > thr0) { int p = atomicAdd(&s_cnt[0], 1); if (p < CAP) { sval[0][p] = q.x; sidx[0][p] = 4 * i + 0; } }
                if (q.y > thr0) { int p = atomicAdd(&s_cnt[0], 1); if (p < CAP) { sval[0][p] = q.y; sidx[0][p] = 4 * i + 1; } }
                if (q.z > thr0) { int p = atomicAdd(&s_cnt[0], 1); if (p < CAP) { sval[0][p] = q.z; sidx[0][p] = 4 * i + 2; } }
                if (q.w > thr0) { int p = atomicAdd(&s_cnt[0], 1); if (p < CAP) { sval[0][p] = q.w; sidx[0][p] = 4 * i + 3; } }
            }
        }
        __syncthreads();
        const int cnt0 = s_cnt[0];

        // ================== row 1 stream (primed) ==================
        // warp0 lags doing row0's Michelot below; its loads are already in flight.
        m = -3.4e38f; qmask = 0u;

        if (warp == 0) {
            // ---- row0 Michelot + loss (overlaps other warps' row1 consume) ----
            const int b = r0 >> 4;
            const float* mrow = mask + (size_t)b * L_DIM;
            float sp2 = 0.f, spm = 0.f;
            if (!fb0 && cnt0 < CAP) {
                float tau = thr0;
                for (int iter = 0; iter < 64; iter++) {
                    float s = 0.f; int c = 0;
                    for (int i = lane; i < cnt0; i += 32) {
                        float v = sval[0][i];
                        if (v > tau) { s += v; c++; }
                    }
                    #pragma unroll
                    for (int o = 16; o; o >>= 1) {
                        s += __shfl_xor_sync(0xffffffffu, s, o);
                        c += __shfl_xor_sync(0xffffffffu, c, o);
                    }
                    float nt = (s - 1.0f) / (float)c;
                    if (nt == tau) break;
                    tau = nt;
                }
                for (int i = lane; i < cnt0; i += 32) {
                    float p = sval[0][i] - tau;
                    if (p > 0.f) { sp2 += p * p; spm += mrow[sidx[0][i]] * p; }
                }
            } else {
                // fallback (≈never): exact full-row Michelot from L2
                float tau = thr0;
                for (int iter = 0; iter < 64; iter++) {
                    float s = 0.f; int c = 0;
                    for (int i = lane; i < Q_DIM; i += 32) {
                        float4 q = za[i];
                        if (q.x > tau) { s += q.x; c++; }
                        if (q.y > tau) { s += q.y; c++; }
                        if (q.z > tau) { s += q.z; c++; }
                        if (q.w > tau) { s += q.w; c++; }
                    }
                    #pragma unroll
                    for (int o = 16; o; o >>= 1) {
                        s += __shfl_xor_sync(0xffffffffu, s, o);
                        c += __shfl_xor_sync(0xffffffffu, c, o);
                    }
                    float nt = (s - 1.0f) / (float)c;
                    if (nt == tau) break;
                    tau = nt;
                }
                for (int i = lane; i < Q_DIM; i += 32) {
                    float4 q = za[i];
                    float px = q.x - tau, py = q.y - tau, pz = q.z - tau, pw = q.w - tau;
                    if (px > 0.f) { sp2 += px * px; spm += mrow[4 * i + 0] * px; }
                    if (py > 0.f) { sp2 += py * py; spm += mrow[4 * i + 1] * py; }
                    if (pz > 0.f) { sp2 += pz * pz; spm += mrow[4 * i + 2] * pz; }
                    if (pw > 0.f) { sp2 += pw * pw; spm += mrow[4 * i + 3] * pw; }
                }
            }
            #pragma unroll
            for (int o = 16; o; o >>= 1) {
                sp2 += __shfl_xor_sync(0xffffffffu, sp2, o);
                spm += __shfl_xor_sync(0xffffffffu, spm, o);
            }
            if (lane == 0) { g_sp2[r0] = sp2; g_spm[r0] = spm; }
        }

        // consume primed groups 0,1 then stream remaining groups of row1
        #pragma unroll
        for (int k = 0; k < DEPTH; k++) {
            float vm = fmaxf(fmaxf(p0[k].x, p0[k].y), fmaxf(p0[k].z, p0[k].w));
            m = fmaxf(m, vm);
            qmask |= (vm > THR_FIXED ? 1u : 0u) << k;
        }
        #pragma unroll
        for (int k = 0; k < DEPTH; k++) a[k] = zb[tid + (2 * DEPTH + k) * THREADS];
        #pragma unroll
        for (int k = 0; k < DEPTH; k++) {
            float vm = fmaxf(fmaxf(p1[k].x, p1[k].y), fmaxf(p1[k].z, p1[k].w));
            m = fmaxf(m, vm);
            qmask |= (vm > THR_FIXED ? 1u : 0u) << (DEPTH + k);
        }
        #pragma unroll
        for (int k = 0; k < DEPTH; k++) nb[k] = zb[tid + (3 * DEPTH + k) * THREADS];
        #pragma unroll
        for (int k = 0; k < DEPTH; k++) {
            float vm = fmaxf(fmaxf(a[k].x, a[k].y), fmaxf(a[k].z, a[k].w));
            m = fmaxf(m, vm);
            qmask |= (vm > THR_FIXED ? 1u : 0u) << (2 * DEPTH + k);
        }
        #pragma unroll
        for (int k = 0; k < DEPTH; k++) {
            float vm = fmaxf(fmaxf(nb[k].x, nb[k].y), fmaxf(nb[k].z, nb[k].w));
            m = fmaxf(m, vm);
            qmask |= (vm > THR_FIXED ? 1u : 0u) << (3 * DEPTH + k);
        }

        // ================== row 1 tail ==================
        #pragma unroll
        for (int o = 16; o; o >>= 1) m = fmaxf(m, __shfl_xor_sync(0xffffffffu, m, o));
        if (lane == 0) s_red[warp] = m;
        __syncthreads();
        if (tid == 0) {
            float t = s_red[0];
            #pragma unroll
            for (int w = 1; w < THREADS / 32; w++) t = fmaxf(t, s_red[w]);
            s_max = t;
        }
        __syncthreads();
        const float thr1 = s_max - 1.0f;
        const bool fb1 = (thr1 < THR_FIXED);
        if (!fb1) {
            unsigned int qm = qmask;
            while (qm) {
                int j = __ffs(qm) - 1;
                qm &= qm - 1u;
                int i = tid + j * THREADS;
                float4 q = zb[i];
                if (q.x > thr1) { int p = atomicAdd(&s_cnt[1], 1); if (p < CAP) { sval[1][p] = q.x; sidx[1][p] = 4 * i + 0; } }
                if (q.y > thr1) { int p = atomicAdd(&s_cnt[1], 1); if (p < CAP) { sval[1][p] = q.y; sidx[1][p] = 4 * i + 1; } }
                if (q.z > thr1) { int p = atomicAdd(&s_cnt[1], 1); if (p < CAP) { sval[1][p] = q.z; sidx[1][p] = 4 * i + 2; } }
                if (q.w > thr1) { int p = atomicAdd(&s_cnt[1], 1); if (p < CAP) { sval[1][p] = q.w; sidx[1][p] = 4 * i + 3; } }
            }
        }
        __syncthreads();
        const int cnt1 = s_cnt[1];

        if (warp == 0) {
            const int b = r1 >> 4;
            const float* mrow = mask + (size_t)b * L_DIM;
            float sp2 = 0.f, spm = 0.f;
            if (!fb1 && cnt1 < CAP) {
                float tau = thr1;
                for (int iter = 0; iter < 64; iter++) {
                    float s = 0.f; int c = 0;
                    for (int i = lane; i < cnt1; i += 32) {
                        float v = sval[1][i];
                        if (v > tau) { s += v; c++; }
                    }
                    #pragma unroll
                    for (int o = 16; o; o >>= 1) {
                        s += __shfl_xor_sync(0xffffffffu, s, o);
                        c += __shfl_xor_sync(0xffffffffu, c, o);
                    }
                    float nt = (s - 1.0f) / (float)c;
                    if (nt == tau) break;
                    tau = nt;
                }
                for (int i = lane; i < cnt1; i += 32) {
                    float p = sval[1][i] - tau;
                    if (p > 0.f) { sp2 += p * p; spm += mrow[sidx[1][i]] * p; }
                }
            } else {
                float tau = thr1;
                for (int iter = 0; iter < 64; iter++) {
                    float s = 0.f; int c = 0;
                    for (int i = lane; i < Q_DIM; i += 32) {
                        float4 q = zb[i];
                        if (q.x > tau) { s += q.x; c++; }
                        if (q.y > tau) { s += q.y; c++; }
                        if (q.z > tau) { s += q.z; c++; }
                        if (q.w > tau) { s += q.w; c++; }
                    }
                    #pragma unroll
                    for (int o = 16; o; o >>= 1) {
                        s += __shfl_xor_sync(0xffffffffu, s, o);
                        c += __shfl_xor_sync(0xffffffffu, c, o);
                    }
                    float nt = (s - 1.0f) / (float)c;
                    if (nt == tau) break;
                    tau = nt;
                }
                for (int i = lane; i < Q_DIM; i += 32) {
                    float4 q = zb[i];
                    float px = q.x - tau, py = q.y - tau, pz = q.z - tau, pw = q.w - tau;
                    if (px > 0.f) { sp2 += px * px; spm += mrow[4 * i + 0] * px; }
                    if (py > 0.f) { sp2 += py * py; spm += mrow[4 * i + 1] * py; }
                    if (pz > 0.f) { sp2 += pz * pz; spm += mrow[4 * i + 2] * pz; }
                    if (pw > 0.f) { sp2 += pw * pw; spm += mrow[4 * i + 3] * pw; }
                }
            }
            #pragma unroll
            for (int o = 16; o; o >>= 1) {
                sp2 += __shfl_xor_sync(0xffffffffu, sp2, o);
                spm += __shfl_xor_sync(0xffffffffu, spm, o);
            }
            if (lane == 0) { g_sp2[r1] = sp2; g_spm[r1] = spm; }
        }
    }

    // ------------- last-block-done final reduction (deterministic) ---------
    __syncthreads();
    __threadfence();
    if (tid == 0) s_ticket = atomicAdd(&g_done, 1u);
    __syncthreads();
    if (s_ticket == TOTAL_BLOCKS - 1) {
        float acc = 0.f;
        #pragma unroll
        for (int j = 0; j < N_ROWS / THREADS; j++) {
            int r = tid + j * THREADS;
            int b = r >> 4;
            float inv_n = 1.0f / fmaxf(g_nmask[b], 1e-12f);
            acc += 0.5f * g_sp2[r] - inv_n * g_spm[r] + 0.5f * inv_n;
        }
        s_fin[tid] = acc;
        __syncthreads();
        #pragma unroll
        for (int o = THREADS / 2; o > 0; o >>= 1) {
            if (tid < o) s_fin[tid] += s_fin[tid + o];
            __syncthreads();
        }
        if (tid == 0) {
            out[0] = s_fin[0] * (1.0f / (float)N_ROWS);
            g_done = 0;        // reset for next graph replay
        }
    }
}

// ---------------------------------------------------------------------------
extern "C" void kernel_launch(void* const* d_in, const int* in_sizes, int n_in,
                              void* d_out, int out_size) {
    const float* logits = (const float*)d_in[0];   // (64,16,16384) fp32
    const float* mask   = (const float*)d_in[1];   // (64,16384) fp32
    float* out = (float*)d_out;

    fused_kernel<<<TOTAL_BLOCKS, THREADS>>>(logits, mask, out);
}